// round 7
// baseline (speedup 1.0000x reference)
#include <cuda_runtime.h>

#define NGR 16384
#define NPG 8
#define NNODES (NGR*NPG)
#define EPG 56
#define EPS_BN 1e-5f
#define SLOPE 0.01f

// ---------------- device scratch (static, allowed) ----------------
__device__ float g_A[NGR*64];          // per-graph 8x8 aggregation matrices
__device__ float g_y1[NNODES*16];
__device__ float g_y2[NNODES*16];
__device__ float g_y3[NNODES*32];
__device__ float g_y4[NNODES*64];
__device__ float g_y5[NNODES*128];
__device__ float g_sum[5*128];
__device__ float g_sq [5*128];

__device__ __forceinline__ float lrelu(float x) { return x >= 0.f ? x : SLOPE*x; }

template<int IDX> __device__ __forceinline__ float* buf_ptr() {
    if constexpr (IDX == 1) return g_y1;
    else if constexpr (IDX == 2) return g_y2;
    else if constexpr (IDX == 3) return g_y3;
    else if constexpr (IDX == 4) return g_y4;
    else return g_y5;
}

// ---------------- stats zeroing ----------------
__global__ void zero_stats_kernel() {
    int t = threadIdx.x;
    if (t < 5*128) { g_sum[t] = 0.f; g_sq[t] = 0.f; }
}

// ---------------- build per-graph 8x8 aggregation matrix ----------------
// warp per graph; edges are graph-major blocks of 56 (fixed generator).
__global__ void __launch_bounds__(256) build_A_kernel(
    const int* __restrict__ ei, const float* __restrict__ ew, int E)
{
    __shared__ float          s_w[8][EPG];
    __shared__ unsigned char  s_s[8][EPG];
    __shared__ unsigned char  s_d[8][EPG];
    __shared__ float          s_dis[8][8];
    __shared__ float          s_A[8][64];

    const int warp = threadIdx.x >> 5, lane = threadIdx.x & 31;
    const int g = blockIdx.x * 8 + warp;
    const int* srcp = ei;
    const int* dstp = ei + E;
    const int ebase = g * EPG;
    const int nbase = g * NPG;

    for (int i = lane; i < EPG; i += 32) {
        s_s[warp][i] = (unsigned char)(srcp[ebase+i] - nbase);
        s_d[warp][i] = (unsigned char)(dstp[ebase+i] - nbase);
        s_w[warp][i] = ew[ebase+i];
    }
    __syncwarp();
    if (lane < 8) {
        float deg = 1.0f;  // self loop
        for (int i = 0; i < EPG; i++)
            if (s_d[warp][i] == lane) deg += s_w[warp][i];
        s_dis[warp][lane] = rsqrtf(deg);
    }
    __syncwarp();
    if (lane < 8) {
        float dis = s_dis[warp][lane];
        s_A[warp][lane*8 + lane] = dis*dis;   // self-loop term 1/deg
    }
    for (int i = lane; i < EPG; i += 32) {
        int s = s_s[warp][i], d = s_d[warp][i];
        s_A[warp][d*8 + s] = s_dis[warp][s] * s_w[warp][i] * s_dis[warp][d];
    }
    __syncwarp();
    for (int i = lane; i < 64; i += 32) g_A[(size_t)g*64 + i] = s_A[warp][i];
}

// ---------------- fused layer kernel ----------------
// computes y = A_agg @ (lrelu(bn(x)) @ W) + b, accumulates per-channel sum/sumsq
template<int D_IN, int D_IN_PAD, int D_OUT, int CH, bool BN_IN,
         int IN_BUF, int OUT_BUF, int SIN, int SOUT>
__global__ void __launch_bounds__(256) layer_kernel(
    const float* __restrict__ xin_arg,
    const float* __restrict__ W, const float* __restrict__ bias,
    const float* __restrict__ in_g, const float* __restrict__ in_be)
{
    constexpr int GPB   = 8;           // graphs per block (warp per graph)
    constexpr int NODES = GPB * NPG;   // 64
    constexpr int WSZ   = D_IN_PAD * D_OUT;
    constexpr int ZSZ   = NODES * D_IN_PAD;

    extern __shared__ float sm[];
    float* W_sh  = sm;
    float* z_sh  = W_sh + WSZ;
    float* A_sh  = z_sh + ZSZ;
    float* red   = A_sh + GPB*64;
    float* sc_sh = red + 2*D_OUT;
    float* sh_sh = sc_sh + D_IN;

    const float* xin = (IN_BUF > 0) ? buf_ptr<IN_BUF>() : xin_arg;
    float* yout = buf_ptr<OUT_BUF>();
    float* out_sum = g_sum + SOUT;
    float* out_sq  = g_sq  + SOUT;

    const int t = threadIdx.x;
    if (t < 2*D_OUT) red[t] = 0.f;
    if (BN_IN && t < D_IN) {
        const float inv_n = 1.0f / (float)NNODES;
        float m  = g_sum[SIN + t] * inv_n;
        float v  = g_sq [SIN + t] * inv_n - m*m;
        float sc = in_g[t] * rsqrtf(v + EPS_BN);
        sc_sh[t] = sc;
        sh_sh[t] = in_be[t] - m*sc;
    }
    for (int i = t; i < WSZ; i += 256) W_sh[i] = (i < D_IN*D_OUT) ? W[i] : 0.f;
    {
        const float* Ag = g_A + (size_t)blockIdx.x * (GPB*64);
        for (int i = t; i < GPB*64; i += 256) A_sh[i] = Ag[i];
    }
    __syncthreads();

    // load x tile -> apply bn+lrelu -> z_sh
    {
        const float* xb = xin + (size_t)blockIdx.x * NODES * D_IN;
        if (D_IN_PAD == D_IN && (D_IN % 4) == 0) {
            for (int i = t; i < NODES*D_IN/4; i += 256) {
                float4 v = reinterpret_cast<const float4*>(xb)[i];
                if (BN_IN) {
                    int c = (i*4) % D_IN;
                    v.x = lrelu(sc_sh[c+0]*v.x + sh_sh[c+0]);
                    v.y = lrelu(sc_sh[c+1]*v.y + sh_sh[c+1]);
                    v.z = lrelu(sc_sh[c+2]*v.z + sh_sh[c+2]);
                    v.w = lrelu(sc_sh[c+3]*v.w + sh_sh[c+3]);
                }
                reinterpret_cast<float4*>(z_sh)[i] = v;
            }
        } else {
            for (int i = t; i < ZSZ; i += 256) {
                int node = i / D_IN_PAD, c = i % D_IN_PAD;
                float v = 0.f;
                if (c < D_IN) {
                    v = xb[node*D_IN + c];
                    if (BN_IN) v = lrelu(sc_sh[c]*v + sh_sh[c]);
                }
                z_sh[i] = v;
            }
        }
    }
    __syncthreads();

    const int warp = t >> 5, lane = t & 31;
    const int c0 = lane * CH;
    if (c0 < D_OUT) {
        float acc[NPG][CH];
        #pragma unroll
        for (int n = 0; n < NPG; n++)
            #pragma unroll
            for (int j = 0; j < CH; j++) acc[n][j] = 0.f;

        const float* zw = z_sh + warp * NPG * D_IN_PAD;
        #pragma unroll 4
        for (int k = 0; k < D_IN_PAD; k += 4) {
            float wv[4][CH];
            #pragma unroll
            for (int kk = 0; kk < 4; kk++) {
                const float* wr = W_sh + (k+kk)*D_OUT + c0;
                if constexpr (CH == 4) {
                    float4 w4 = *reinterpret_cast<const float4*>(wr);
                    wv[kk][0]=w4.x; wv[kk][1]=w4.y; wv[kk][2]=w4.z; wv[kk][3]=w4.w;
                } else if constexpr (CH == 2) {
                    float2 w2 = *reinterpret_cast<const float2*>(wr);
                    wv[kk][0]=w2.x; wv[kk][1]=w2.y;
                } else {
                    wv[kk][0] = wr[0];
                }
            }
            #pragma unroll
            for (int n = 0; n < NPG; n++) {
                float4 z = *reinterpret_cast<const float4*>(zw + n*D_IN_PAD + k);
                #pragma unroll
                for (int j = 0; j < CH; j++)
                    acc[n][j] += z.x*wv[0][j] + z.y*wv[1][j] + z.z*wv[2][j] + z.w*wv[3][j];
            }
        }

        float bcol[CH];
        #pragma unroll
        for (int j = 0; j < CH; j++) bcol[j] = bias[c0+j];
        float ssum[CH], ssq[CH];
        #pragma unroll
        for (int j = 0; j < CH; j++) { ssum[j]=0.f; ssq[j]=0.f; }

        const float* Aw = A_sh + warp*64;
        float* yb = yout + ((size_t)blockIdx.x*NODES + warp*NPG) * D_OUT + c0;
        #pragma unroll
        for (int n = 0; n < NPG; n++) {
            float y[CH];
            #pragma unroll
            for (int j = 0; j < CH; j++) y[j] = bcol[j];
            #pragma unroll
            for (int m = 0; m < NPG; m++) {
                float a = Aw[n*8 + m];
                #pragma unroll
                for (int j = 0; j < CH; j++) y[j] += a * acc[m][j];
            }
            #pragma unroll
            for (int j = 0; j < CH; j++) { ssum[j] += y[j]; ssq[j] += y[j]*y[j]; }
            float* yo = yb + n*D_OUT;
            if constexpr (CH == 4)
                *reinterpret_cast<float4*>(yo) = make_float4(y[0],y[1],y[2],y[3]);
            else if constexpr (CH == 2)
                *reinterpret_cast<float2*>(yo) = make_float2(y[0],y[1]);
            else
                yo[0] = y[0];
        }
        #pragma unroll
        for (int j = 0; j < CH; j++) {
            atomicAdd(&red[c0+j],        ssum[j]);
            atomicAdd(&red[D_OUT+c0+j],  ssq[j]);
        }
    }
    __syncthreads();
    if (t < D_OUT) {
        atomicAdd(&out_sum[t], red[t]);
        atomicAdd(&out_sq [t], red[D_OUT+t]);
    }
}

// ---------------- final: bn+lrelu on y5, mean-pool, MLP ----------------
__global__ void __launch_bounds__(256) final_kernel(
    const float* __restrict__ g5, const float* __restrict__ be5,
    const float* __restrict__ fc1w, const float* __restrict__ fc1b,
    const float* __restrict__ fc2w, const float* __restrict__ fc2b,
    const float* __restrict__ ow,   const float* __restrict__ ob,
    float* __restrict__ out)
{
    __shared__ float sc[128], sh[128];
    __shared__ float w1s[128*30];
    __shared__ float b1s[30], w2s[30*20], b2s[20], w3s[20];
    __shared__ float P[8][128];
    __shared__ float Z1[8][30];

    const int t = threadIdx.x;
    if (t < 128) {
        const float inv_n = 1.0f / (float)NNODES;
        float m = g_sum[512 + t] * inv_n;
        float v = g_sq [512 + t] * inv_n - m*m;
        float s = g5[t] * rsqrtf(v + EPS_BN);
        sc[t] = s; sh[t] = be5[t] - m*s;
    }
    for (int i = t; i < 128*30; i += 256) w1s[i] = fc1w[i];
    if (t < 30) b1s[t] = fc1b[t];
    for (int i = t; i < 600; i += 256) w2s[i] = fc2w[i];
    if (t < 20) b2s[t] = fc2b[t];
    if (t < 20) w3s[t] = ow[t];
    __syncthreads();

    const int warp = t >> 5, lane = t & 31;
    const int g = blockIdx.x * 8 + warp;
    const int c0 = lane * 4;

    float p0=0.f, p1=0.f, p2=0.f, p3=0.f;
    const float* yb = g_y5 + (size_t)g * NPG * 128 + c0;
    #pragma unroll
    for (int n = 0; n < NPG; n++) {
        float4 v = *reinterpret_cast<const float4*>(yb + n*128);
        p0 += lrelu(sc[c0+0]*v.x + sh[c0+0]);
        p1 += lrelu(sc[c0+1]*v.y + sh[c0+1]);
        p2 += lrelu(sc[c0+2]*v.z + sh[c0+2]);
        p3 += lrelu(sc[c0+3]*v.w + sh[c0+3]);
    }
    const float inv8 = 1.0f / (float)NPG;
    P[warp][c0+0] = p0*inv8; P[warp][c0+1] = p1*inv8;
    P[warp][c0+2] = p2*inv8; P[warp][c0+3] = p3*inv8;
    __syncwarp();

    if (lane < 30) {
        float z1 = b1s[lane];
        #pragma unroll 8
        for (int k = 0; k < 128; k++) z1 += P[warp][k] * w1s[k*30 + lane];
        Z1[warp][lane] = lrelu(z1);
    }
    __syncwarp();

    float z2 = 0.f;
    if (lane < 20) {
        float a = b2s[lane];
        #pragma unroll
        for (int k = 0; k < 30; k++) a += Z1[warp][k] * w2s[k*20 + lane];
        z2 = lrelu(a) * w3s[lane];
    }
    #pragma unroll
    for (int off = 16; off > 0; off >>= 1)
        z2 += __shfl_down_sync(0xffffffffu, z2, off);
    if (lane == 0) out[g] = z2 + ob[0];
}

// ---------------- launch ----------------
static constexpr int smem_bytes(int din, int dinp, int dout) {
    return (dinp*dout + 64*dinp + 8*64 + 2*dout + 2*din) * 4;
}

extern "C" void kernel_launch(void* const* d_in, const int* in_sizes, int n_in,
                              void* d_out, int out_size)
{
    const float* x   = (const float*)d_in[0];
    const int*   ei  = (const int*)  d_in[1];
    const float* ea  = (const float*)d_in[2];
    const float* w1  = (const float*)d_in[4],  *b1  = (const float*)d_in[5];
    const float* ga1 = (const float*)d_in[6],  *be1 = (const float*)d_in[7];
    const float* w2  = (const float*)d_in[8],  *b2  = (const float*)d_in[9];
    const float* ga2 = (const float*)d_in[10], *be2 = (const float*)d_in[11];
    const float* w3  = (const float*)d_in[12], *b3  = (const float*)d_in[13];
    const float* ga3 = (const float*)d_in[14], *be3 = (const float*)d_in[15];
    const float* w4  = (const float*)d_in[16], *b4  = (const float*)d_in[17];
    const float* ga4 = (const float*)d_in[18], *be4 = (const float*)d_in[19];
    const float* w5  = (const float*)d_in[20], *b5  = (const float*)d_in[21];
    const float* ga5 = (const float*)d_in[22], *be5 = (const float*)d_in[23];
    const float* fc1w = (const float*)d_in[24], *fc1b = (const float*)d_in[25];
    const float* fc2w = (const float*)d_in[26], *fc2b = (const float*)d_in[27];
    const float* ow   = (const float*)d_in[28], *ob   = (const float*)d_in[29];
    float* out = (float*)d_out;

    const int E = in_sizes[1] / 2;

    // opt-in smem for layer 5 (> 48KB)
    cudaFuncSetAttribute(layer_kernel<64,64,128,4,true,4,5,384,512>,
                         cudaFuncAttributeMaxDynamicSharedMemorySize,
                         smem_bytes(64,64,128));

    zero_stats_kernel<<<1, 640>>>();
    build_A_kernel<<<NGR/8, 256>>>(ei, ea, E);

    layer_kernel< 6,  8, 16, 1, false, 0, 1,   0,   0>
        <<<NGR/8, 256, smem_bytes(6,8,16)>>>(x, w1, b1, nullptr, nullptr);
    layer_kernel<16, 16, 16, 1, true,  1, 2,   0, 128>
        <<<NGR/8, 256, smem_bytes(16,16,16)>>>(nullptr, w2, b2, ga1, be1);
    layer_kernel<16, 16, 32, 1, true,  2, 3, 128, 256>
        <<<NGR/8, 256, smem_bytes(16,16,32)>>>(nullptr, w3, b3, ga2, be2);
    layer_kernel<32, 32, 64, 2, true,  3, 4, 256, 384>
        <<<NGR/8, 256, smem_bytes(32,32,64)>>>(nullptr, w4, b4, ga3, be3);
    layer_kernel<64, 64,128, 4, true,  4, 5, 384, 512>
        <<<NGR/8, 256, smem_bytes(64,64,128)>>>(nullptr, w5, b5, ga4, be4);

    final_kernel<<<NGR/8, 256>>>(ga5, be5, fc1w, fc1b, fc2w, fc2b, ow, ob, out);
}

// round 11
// speedup vs baseline: 1.0586x; 1.0586x over previous
#include <cuda_runtime.h>
#include <cuda_bf16.h>
#include <cstdint>

#define NGR 16384
#define NPG 8
#define NNODES (NGR*NPG)
#define EPG 56
#define EPS_BN 1e-5f
#define SLOPE 0.01f

// ---------------- device scratch ----------------
__device__ float g_A[NGR*64];
__device__ float g_y1[NNODES*16];
__device__ float g_y2[NNODES*16];
__device__ float g_y3[NNODES*32];
__device__ float g_y4[NNODES*64];
__device__ float g_y5[NNODES*128];
__device__ float g_sum[5*128];
__device__ float g_sq [5*128];
__device__ uint4 g_W4f[2*8*32];    // (K/16)*(N/8)*32 fragments for W4
__device__ uint4 g_W5f[4*16*32];   // for W5

__device__ __forceinline__ float lrelu(float x) { return x >= 0.f ? x : SLOPE*x; }

template<int IDX> __device__ __forceinline__ float* buf_ptr() {
    if constexpr (IDX == 1) return g_y1;
    else if constexpr (IDX == 2) return g_y2;
    else if constexpr (IDX == 3) return g_y3;
    else if constexpr (IDX == 4) return g_y4;
    else return g_y5;
}
template<int SEL> __device__ __forceinline__ const uint4* wf_ptr() {
    if constexpr (SEL == 4) return g_W4f; else return g_W5f;
}

__device__ __forceinline__ void mma_bf16(float* c, const uint32_t* a, uint32_t b0, uint32_t b1) {
    asm volatile("mma.sync.aligned.m16n8k16.row.col.f32.bf16.bf16.f32 "
        "{%0,%1,%2,%3},{%4,%5,%6,%7},{%8,%9},{%0,%1,%2,%3};"
        : "+f"(c[0]),"+f"(c[1]),"+f"(c[2]),"+f"(c[3])
        : "r"(a[0]),"r"(a[1]),"r"(a[2]),"r"(a[3]),"r"(b0),"r"(b1));
}

// ---------------- stats zeroing ----------------
__global__ void zero_stats_kernel() {
    int t = threadIdx.x;
    if (t < 5*128) { g_sum[t] = 0.f; g_sq[t] = 0.f; }
}

// ---------------- W fragment prep (bf16 hi/lo split, mma B layout) ----------------
__device__ __forceinline__ uint32_t pack_bf2(float a, float b) {
    __nv_bfloat162 p; p.x = __float2bfloat16(a); p.y = __float2bfloat16(b);
    return *(uint32_t*)&p;
}
__device__ __forceinline__ void fill_wfrag(uint4* dst, const float* W, int N, int idx) {
    const int NT = N/8;
    int kt = idx/(NT*32); int rem = idx%(NT*32);
    int nt = rem/32;      int l  = rem%32;
    int grp = l>>2, tq = l&3;
    int col = nt*8 + grp;
    int k0 = kt*16 + 2*tq;
    float w00 = W[(k0  )*N+col], w01 = W[(k0+1)*N+col];
    float w10 = W[(k0+8)*N+col], w11 = W[(k0+9)*N+col];
    float h00 = __bfloat162float(__float2bfloat16(w00));
    float h01 = __bfloat162float(__float2bfloat16(w01));
    float h10 = __bfloat162float(__float2bfloat16(w10));
    float h11 = __bfloat162float(__float2bfloat16(w11));
    uint4 o;
    o.x = pack_bf2(w00, w01);            // b0 hi
    o.y = pack_bf2(w10, w11);            // b1 hi
    o.z = pack_bf2(w00-h00, w01-h01);    // b0 lo
    o.w = pack_bf2(w10-h10, w11-h11);    // b1 lo
    dst[idx] = o;
}
__global__ void prep_w_kernel(const float* __restrict__ W4, const float* __restrict__ W5) {
    int idx = blockIdx.x*256 + threadIdx.x;
    if (idx < 512)       fill_wfrag(g_W4f, W4, 64,  idx);
    else if (idx < 2560) fill_wfrag(g_W5f, W5, 128, idx-512);
}

// ---------------- build per-graph 8x8 aggregation matrix ----------------
__global__ void __launch_bounds__(256) build_A_kernel(
    const int* __restrict__ ei, const float* __restrict__ ew, int E)
{
    __shared__ float          s_w[8][EPG];
    __shared__ unsigned char  s_s[8][EPG];
    __shared__ unsigned char  s_d[8][EPG];
    __shared__ float          s_dis[8][8];
    __shared__ float          s_A[8][64];

    const int warp = threadIdx.x >> 5, lane = threadIdx.x & 31;
    const int g = blockIdx.x * 8 + warp;
    const int* srcp = ei;
    const int* dstp = ei + E;
    const int ebase = g * EPG;
    const int nbase = g * NPG;

    for (int i = lane; i < EPG; i += 32) {
        s_s[warp][i] = (unsigned char)(srcp[ebase+i] - nbase);
        s_d[warp][i] = (unsigned char)(dstp[ebase+i] - nbase);
        s_w[warp][i] = ew[ebase+i];
    }
    __syncwarp();
    if (lane < 8) {
        float deg = 1.0f;
        for (int i = 0; i < EPG; i++)
            if (s_d[warp][i] == lane) deg += s_w[warp][i];
        s_dis[warp][lane] = rsqrtf(deg);
    }
    __syncwarp();
    if (lane < 8) {
        float dis = s_dis[warp][lane];
        s_A[warp][lane*8 + lane] = dis*dis;
    }
    for (int i = lane; i < EPG; i += 32) {
        int s = s_s[warp][i], d = s_d[warp][i];
        s_A[warp][d*8 + s] = s_dis[warp][s] * s_w[warp][i] * s_dis[warp][d];
    }
    __syncwarp();
    for (int i = lane; i < 64; i += 32) g_A[(size_t)g*64 + i] = s_A[warp][i];
}

// ---------------- fp32 layer kernel (small dims), GPW graphs per warp ----------------
template<int D_IN, int D_IN_PAD, int D_OUT, int CH, int GPW, bool BN_IN,
         int IN_BUF, int OUT_BUF, int SIN, int SOUT>
__global__ void __launch_bounds__(256) layer_kernel(
    const float* __restrict__ xin_arg,
    const float* __restrict__ W, const float* __restrict__ bias,
    const float* __restrict__ in_g, const float* __restrict__ in_be)
{
    constexpr int GPB   = 8 * GPW;
    constexpr int NODES = GPB * NPG;
    constexpr int WSZ   = D_IN_PAD * D_OUT;
    constexpr int ZSZ   = NODES * D_IN_PAD;

    extern __shared__ float sm[];
    float* W_sh  = sm;
    float* z_sh  = W_sh + WSZ;
    float* A_sh  = z_sh + ZSZ;
    float* red   = A_sh + GPB*64;
    float* sc_sh = red + 2*D_OUT;
    float* sh_sh = sc_sh + D_IN;

    const float* xin = (IN_BUF > 0) ? buf_ptr<IN_BUF>() : xin_arg;
    float* yout = buf_ptr<OUT_BUF>();

    const int t = threadIdx.x;
    if (t < 2*D_OUT) red[t] = 0.f;
    if (BN_IN && t < D_IN) {
        const float inv_n = 1.0f / (float)NNODES;
        float m  = g_sum[SIN + t] * inv_n;
        float v  = g_sq [SIN + t] * inv_n - m*m;
        float sc = in_g[t] * rsqrtf(v + EPS_BN);
        sc_sh[t] = sc;
        sh_sh[t] = in_be[t] - m*sc;
    }
    for (int i = t; i < WSZ; i += 256) W_sh[i] = (i < D_IN*D_OUT) ? W[i] : 0.f;
    {
        const float* Ag = g_A + (size_t)blockIdx.x * (GPB*64);
        for (int i = t; i < GPB*64; i += 256) A_sh[i] = Ag[i];
    }
    __syncthreads();

    {
        const float* xb = xin + (size_t)blockIdx.x * NODES * D_IN;
        if (D_IN_PAD == D_IN && (D_IN % 4) == 0) {
            for (int i = t; i < NODES*D_IN/4; i += 256) {
                float4 v = reinterpret_cast<const float4*>(xb)[i];
                if (BN_IN) {
                    int c = (i*4) % D_IN;
                    v.x = lrelu(sc_sh[c+0]*v.x + sh_sh[c+0]);
                    v.y = lrelu(sc_sh[c+1]*v.y + sh_sh[c+1]);
                    v.z = lrelu(sc_sh[c+2]*v.z + sh_sh[c+2]);
                    v.w = lrelu(sc_sh[c+3]*v.w + sh_sh[c+3]);
                }
                reinterpret_cast<float4*>(z_sh)[i] = v;
            }
        } else {
            for (int i = t; i < ZSZ; i += 256) {
                int node = i / D_IN_PAD, c = i % D_IN_PAD;
                float v = 0.f;
                if (c < D_IN) {
                    v = xb[node*D_IN + c];
                    if (BN_IN) v = lrelu(sc_sh[c]*v + sh_sh[c]);
                }
                z_sh[i] = v;
            }
        }
    }
    __syncthreads();

    const int warp = t >> 5, lane = t & 31;
    int graph_l, c0;
    if constexpr (GPW == 2) { graph_l = warp*2 + (lane >> 4); c0 = (lane & 15) * CH; }
    else                    { graph_l = warp;                 c0 = lane * CH; }

    if (c0 < D_OUT) {
        float acc[NPG][CH];
        #pragma unroll
        for (int n = 0; n < NPG; n++)
            #pragma unroll
            for (int j = 0; j < CH; j++) acc[n][j] = 0.f;

        const float* zw = z_sh + graph_l * NPG * D_IN_PAD;
        #pragma unroll 4
        for (int k = 0; k < D_IN_PAD; k += 4) {
            float wv[4][CH];
            #pragma unroll
            for (int kk = 0; kk < 4; kk++) {
                const float* wr = W_sh + (k+kk)*D_OUT + c0;
                if constexpr (CH == 2) {
                    float2 w2 = *reinterpret_cast<const float2*>(wr);
                    wv[kk][0]=w2.x; wv[kk][1]=w2.y;
                } else {
                    wv[kk][0] = wr[0];
                }
            }
            #pragma unroll
            for (int n = 0; n < NPG; n++) {
                float4 z = *reinterpret_cast<const float4*>(zw + n*D_IN_PAD + k);
                #pragma unroll
                for (int j = 0; j < CH; j++)
                    acc[n][j] += z.x*wv[0][j] + z.y*wv[1][j] + z.z*wv[2][j] + z.w*wv[3][j];
            }
        }

        float bcol[CH], ssum[CH], ssq[CH];
        #pragma unroll
        for (int j = 0; j < CH; j++) { bcol[j] = bias[c0+j]; ssum[j]=0.f; ssq[j]=0.f; }

        const float* Aw = A_sh + graph_l*64;
        float* yb = yout + ((size_t)blockIdx.x*NODES + graph_l*NPG) * D_OUT + c0;
        #pragma unroll
        for (int n = 0; n < NPG; n++) {
            float y[CH];
            #pragma unroll
            for (int j = 0; j < CH; j++) y[j] = bcol[j];
            #pragma unroll
            for (int m = 0; m < NPG; m++) {
                float a = Aw[n*8 + m];
                #pragma unroll
                for (int j = 0; j < CH; j++) y[j] += a * acc[m][j];
            }
            #pragma unroll
            for (int j = 0; j < CH; j++) { ssum[j] += y[j]; ssq[j] += y[j]*y[j]; }
            float* yo = yb + n*D_OUT;
            if constexpr (CH == 2)
                *reinterpret_cast<float2*>(yo) = make_float2(y[0],y[1]);
            else
                yo[0] = y[0];
        }
        #pragma unroll
        for (int j = 0; j < CH; j++) {
            atomicAdd(&red[c0+j],        ssum[j]);
            atomicAdd(&red[D_OUT+c0+j],  ssq[j]);
        }
    }
    __syncthreads();
    if (t < D_OUT) {
        atomicAdd(&g_sum[SOUT + t], red[t]);
        atomicAdd(&g_sq [SOUT + t], red[D_OUT+t]);
    }
}

// ---------------- tensor-core layer (L4/L5): y = (A lrelu(bn(x))) W + b ----------------
template<int K, int N, int KP, int IN_BUF, int OUT_BUF, int SIN, int SOUT, int WSEL>
__global__ void __launch_bounds__(256) tc_layer_kernel(
    const float* __restrict__ bias,
    const float* __restrict__ in_g, const float* __restrict__ in_be)
{
    constexpr int ROWS = 128, GPB = 16;
    constexpr int KT = K/16, NT = N/8, ZP = ROWS + 1, KQ = K/4;

    extern __shared__ char smraw[];
    uint4* Wf      = (uint4*)smraw;
    float* z_t     = (float*)(Wf + KT*NT*32);
    float* A_sh    = z_t + K*ZP;
    float* bias_sh = A_sh + GPB*64;
    float* sc_sh   = bias_sh + N;
    float* sh_sh   = sc_sh + K;
    float* red     = sh_sh + K;
    float* redq    = red + N;
    __nv_bfloat16* vh = (__nv_bfloat16*)(redq + N);
    __nv_bfloat16* vl = vh + ROWS*KP;

    const int t = threadIdx.x;
    const float* xin = buf_ptr<IN_BUF>() + (size_t)blockIdx.x * ROWS * K;
    float* yout = buf_ptr<OUT_BUF>() + (size_t)blockIdx.x * ROWS * N;

    for (int i = t; i < KT*NT*32; i += 256) Wf[i] = wf_ptr<WSEL>()[i];
    for (int i = t; i < GPB*64; i += 256) A_sh[i] = g_A[(size_t)blockIdx.x*GPB*64 + i];
    if (t < N) { bias_sh[t] = bias[t]; red[t] = 0.f; redq[t] = 0.f; }
    if (t < K) {
        const float inv_n = 1.0f / (float)NNODES;
        float m = g_sum[SIN + t] * inv_n;
        float v = g_sq [SIN + t] * inv_n - m*m;
        float s = in_g[t] * rsqrtf(v + EPS_BN);
        sc_sh[t] = s; sh_sh[t] = in_be[t] - m*s;
    }
    __syncthreads();

    // z = lrelu(bn(x)), stored transposed z_t[k][row]
    for (int i = t; i < ROWS*KQ; i += 256) {
        int r = i / KQ, k = (i % KQ) * 4;
        float4 v = *(const float4*)(xin + r*K + k);
        v.x = lrelu(fmaf(sc_sh[k+0], v.x, sh_sh[k+0]));
        v.y = lrelu(fmaf(sc_sh[k+1], v.y, sh_sh[k+1]));
        v.z = lrelu(fmaf(sc_sh[k+2], v.z, sh_sh[k+2]));
        v.w = lrelu(fmaf(sc_sh[k+3], v.w, sh_sh[k+3]));
        z_t[(k+0)*ZP + r] = v.x;
        z_t[(k+1)*ZP + r] = v.y;
        z_t[(k+2)*ZP + r] = v.z;
        z_t[(k+3)*ZP + r] = v.w;
    }
    __syncthreads();

    // v = A @ z, split to bf16 hi/lo planes
    {
        int r = t & 127, h = t >> 7;
        int g = r >> 3, n = r & 7;
        float a[8];
        #pragma unroll
        for (int m = 0; m < 8; m++) a[m] = A_sh[g*64 + n*8 + m];
        const int k0 = h * (K/2);
        for (int k = k0; k < k0 + K/2; k += 2) {
            float v0 = 0.f, v1 = 0.f;
            #pragma unroll
            for (int m = 0; m < 8; m++) {
                float am = a[m];
                v0 = fmaf(am, z_t[(k  )*ZP + g*8 + m], v0);
                v1 = fmaf(am, z_t[(k+1)*ZP + g*8 + m], v1);
            }
            float h0 = __bfloat162float(__float2bfloat16(v0));
            float h1 = __bfloat162float(__float2bfloat16(v1));
            *(uint32_t*)(vh + r*KP + k) = pack_bf2(v0, v1);
            *(uint32_t*)(vl + r*KP + k) = pack_bf2(v0 - h0, v1 - h1);
        }
    }
    __syncthreads();

    // MMA phase: warp w handles rows [w*16, w*16+16)
    const int w = t >> 5, l = t & 31, grp = l >> 2, tq = l & 3;
    const int rowbase = w * 16;
    uint32_t ah[KT][4], al[KT][4];
    #pragma unroll
    for (int kt = 0; kt < KT; kt++) {
        int e0 = (rowbase + grp)*KP + kt*16 + 2*tq;
        int e1 = e0 + 8*KP;
        ah[kt][0] = *(const uint32_t*)(vh + e0);
        ah[kt][1] = *(const uint32_t*)(vh + e1);
        ah[kt][2] = *(const uint32_t*)(vh + e0 + 8);
        ah[kt][3] = *(const uint32_t*)(vh + e1 + 8);
        al[kt][0] = *(const uint32_t*)(vl + e0);
        al[kt][1] = *(const uint32_t*)(vl + e1);
        al[kt][2] = *(const uint32_t*)(vl + e0 + 8);
        al[kt][3] = *(const uint32_t*)(vl + e1 + 8);
    }
    #pragma unroll
    for (int nt = 0; nt < NT; nt++) {
        int c0 = nt*8 + 2*tq;
        float2 bb = *(const float2*)(bias_sh + c0);
        float c[4] = {bb.x, bb.y, bb.x, bb.y};
        #pragma unroll
        for (int kt = 0; kt < KT; kt++) {
            uint4 wfr = Wf[(kt*NT + nt)*32 + l];
            mma_bf16(c, ah[kt], wfr.x, wfr.y);   // hi*hi
            mma_bf16(c, ah[kt], wfr.z, wfr.w);   // hi*lo
            mma_bf16(c, al[kt], wfr.x, wfr.y);   // lo*hi
        }
        float* y0 = yout + (rowbase + grp)*N + c0;
        *(float2*)y0         = make_float2(c[0], c[1]);
        *(float2*)(y0 + 8*N) = make_float2(c[2], c[3]);
        float s0 = c[0]+c[2], s1 = c[1]+c[3];
        float q0 = c[0]*c[0]+c[2]*c[2], q1 = c[1]*c[1]+c[3]*c[3];
        #pragma unroll
        for (int m = 4; m < 32; m <<= 1) {
            s0 += __shfl_xor_sync(0xffffffffu, s0, m);
            s1 += __shfl_xor_sync(0xffffffffu, s1, m);
            q0 += __shfl_xor_sync(0xffffffffu, q0, m);
            q1 += __shfl_xor_sync(0xffffffffu, q1, m);
        }
        if (grp == 0) {
            atomicAdd(&red [c0],   s0); atomicAdd(&red [c0+1], s1);
            atomicAdd(&redq[c0],   q0); atomicAdd(&redq[c0+1], q1);
        }
    }
    __syncthreads();
    if (t < N) {
        atomicAdd(&g_sum[SOUT + t], red[t]);
        atomicAdd(&g_sq [SOUT + t], redq[t]);
    }
}

// ---------------- final: bn+lrelu on y5, mean-pool, MLP ----------------
__global__ void __launch_bounds__(256) final_kernel(
    const float* __restrict__ g5, const float* __restrict__ be5,
    const float* __restrict__ fc1w, const float* __restrict__ fc1b,
    const float* __restrict__ fc2w, const float* __restrict__ fc2b,
    const float* __restrict__ ow,   const float* __restrict__ ob,
    float* __restrict__ out)
{
    __shared__ float sc[128], sh[128];
    __shared__ float w1s[128*30];
    __shared__ float b1s[30], w2s[30*20], b2s[20], w3s[20];
    __shared__ float P[8][128];
    __shared__ float Z1[8][30];

    const int t = threadIdx.x;
    if (t < 128) {
        const float inv_n = 1.0f / (float)NNODES;
        float m = g_sum[512 + t] * inv_n;
        float v = g_sq [512 + t] * inv_n - m*m;
        float s = g5[t] * rsqrtf(v + EPS_BN);
        sc[t] = s; sh[t] = be5[t] - m*s;
    }
    for (int i = t; i < 128*30; i += 256) w1s[i] = fc1w[i];
    if (t < 30) b1s[t] = fc1b[t];
    for (int i = t; i < 600; i += 256) w2s[i] = fc2w[i];
    if (t < 20) b2s[t] = fc2b[t];
    if (t < 20) w3s[t] = ow[t];
    __syncthreads();

    const int warp = t >> 5, lane = t & 31;
    const int g = blockIdx.x * 8 + warp;
    const int c0 = lane * 4;

    float p0=0.f, p1=0.f, p2=0.f, p3=0.f;
    const float* yb = g_y5 + (size_t)g * NPG * 128 + c0;
    #pragma unroll
    for (int n = 0; n < NPG; n++) {
        float4 v = *reinterpret_cast<const float4*>(yb + n*128);
        p0 += lrelu(sc[c0+0]*v.x + sh[c0+0]);
        p1 += lrelu(sc[c0+1]*v.y + sh[c0+1]);
        p2 += lrelu(sc[c0+2]*v.z + sh[c0+2]);
        p3 += lrelu(sc[c0+3]*v.w + sh[c0+3]);
    }
    const float inv8 = 1.0f / (float)NPG;
    P[warp][c0+0] = p0*inv8; P[warp][c0+1] = p1*inv8;
    P[warp][c0+2] = p2*inv8; P[warp][c0+3] = p3*inv8;
    __syncwarp();

    if (lane < 30) {
        float z1 = b1s[lane];
        #pragma unroll 8
        for (int k = 0; k < 128; k++) z1 += P[warp][k] * w1s[k*30 + lane];
        Z1[warp][lane] = lrelu(z1);
    }
    __syncwarp();

    float z2 = 0.f;
    if (lane < 20) {
        float a = b2s[lane];
        #pragma unroll
        for (int k = 0; k < 30; k++) a += Z1[warp][k] * w2s[k*20 + lane];
        z2 = lrelu(a) * w3s[lane];
    }
    #pragma unroll
    for (int off = 16; off > 0; off >>= 1)
        z2 += __shfl_down_sync(0xffffffffu, z2, off);
    if (lane == 0) out[g] = z2 + ob[0];
}

// ---------------- launch ----------------
static constexpr int smem_small(int din, int dinp, int dout, int gpb) {
    return (dinp*dout + gpb*8*dinp + gpb*64 + 2*dout + 2*din) * 4;
}
static constexpr int smem_tc(int K, int N, int KP) {
    return (K/16)*(N/8)*32*16        // Wf
         + K*(128+1)*4               // z_t
         + 16*64*4                   // A_sh
         + (N + 2*K + 2*N)*4         // bias, sc, sh, red, redq
         + 2*128*KP*2;               // vh, vl
}

extern "C" void kernel_launch(void* const* d_in, const int* in_sizes, int n_in,
                              void* d_out, int out_size)
{
    const float* x   = (const float*)d_in[0];
    const int*   ei  = (const int*)  d_in[1];
    const float* ea  = (const float*)d_in[2];
    const float* w1  = (const float*)d_in[4],  *b1  = (const float*)d_in[5];
    const float* ga1 = (const float*)d_in[6],  *be1 = (const float*)d_in[7];
    const float* w2  = (const float*)d_in[8],  *b2  = (const float*)d_in[9];
    const float* ga2 = (const float*)d_in[10], *be2 = (const float*)d_in[11];
    const float* w3  = (const float*)d_in[12], *b3  = (const float*)d_in[13];
    const float* ga3 = (const float*)d_in[14], *be3 = (const float*)d_in[15];
    const float* w4  = (const float*)d_in[16];
    const float* b4  = (const float*)d_in[17];
    const float* ga4 = (const float*)d_in[18], *be4 = (const float*)d_in[19];
    const float* w5  = (const float*)d_in[20];
    const float* b5  = (const float*)d_in[21];
    const float* ga5 = (const float*)d_in[22], *be5 = (const float*)d_in[23];
    const float* fc1w = (const float*)d_in[24], *fc1b = (const float*)d_in[25];
    const float* fc2w = (const float*)d_in[26], *fc2b = (const float*)d_in[27];
    const float* ow   = (const float*)d_in[28], *ob   = (const float*)d_in[29];
    float* out = (float*)d_out;

    const int E = in_sizes[1] / 2;

    cudaFuncSetAttribute(tc_layer_kernel<32, 64,40,3,4,256,384,4>,
                         cudaFuncAttributeMaxDynamicSharedMemorySize, smem_tc(32,64,40));
    cudaFuncSetAttribute(tc_layer_kernel<64,128,72,4,5,384,512,5>,
                         cudaFuncAttributeMaxDynamicSharedMemorySize, smem_tc(64,128,72));

    zero_stats_kernel<<<1, 640>>>();
    build_A_kernel<<<NGR/8, 256>>>(ei, ea, E);
    prep_w_kernel<<<10, 256>>>(w4, w5);

    layer_kernel< 6,  8, 16, 1, 2, false, 0, 1,   0,   0>
        <<<NGR/16, 256, smem_small(6,8,16,16)>>>(x, w1, b1, nullptr, nullptr);
    layer_kernel<16, 16, 16, 1, 2, true,  1, 2,   0, 128>
        <<<NGR/16, 256, smem_small(16,16,16,16)>>>(nullptr, w2, b2, ga1, be1);
    layer_kernel<16, 16, 32, 1, 1, true,  2, 3, 128, 256>
        <<<NGR/8, 256, smem_small(16,16,32,8)>>>(nullptr, w3, b3, ga2, be2);

    tc_layer_kernel<32, 64, 40, 3, 4, 256, 384, 4>
        <<<NNODES/128, 256, smem_tc(32,64,40)>>>(b4, ga3, be3);
    tc_layer_kernel<64,128, 72, 4, 5, 384, 512, 5>
        <<<NNODES/128, 256, smem_tc(64,128,72)>>>(b5, ga4, be4);

    final_kernel<<<NGR/8, 256>>>(ga5, be5, fc1w, fc1b, fc2w, fc2b, ow, ob, out);
}

// round 16
// speedup vs baseline: 1.0829x; 1.0230x over previous
#include <cuda_runtime.h>
#include <cuda_bf16.h>
#include <cuda_fp16.h>
#include <cstdint>

#define NGR 16384
#define NPG 8
#define NNODES (NGR*NPG)
#define EPG 56
#define EPS_BN 1e-5f
#define SLOPE 0.01f

// ---------------- device scratch ----------------
__device__ float  g_A[NGR*64];
__device__ float  g_y1[NNODES*16];
__device__ float  g_y2[NNODES*16];
__device__ float  g_y3[NNODES*32];
__device__ __half g_h4[NNODES*64];
__device__ __half g_h5[NNODES*128];
__device__ float  g_sum[5*128];
__device__ float  g_sq [5*128];
__device__ uint4  g_W4f[2*8*32];
__device__ uint4  g_W5f[4*16*32];

__device__ __forceinline__ float lrelu(float x) { return x >= 0.f ? x : SLOPE*x; }

template<int IDX> __device__ __forceinline__ float* buf_ptr() {
    if constexpr (IDX == 1) return g_y1;
    else if constexpr (IDX == 2) return g_y2;
    else return g_y3;
}
template<int SEL> __device__ __forceinline__ const uint4* wf_ptr() {
    if constexpr (SEL == 4) return g_W4f; else return g_W5f;
}

__device__ __forceinline__ void mma_bf16(float* c, const uint32_t* a, uint32_t b0, uint32_t b1) {
    asm volatile("mma.sync.aligned.m16n8k16.row.col.f32.bf16.bf16.f32 "
        "{%0,%1,%2,%3},{%4,%5,%6,%7},{%8,%9},{%0,%1,%2,%3};"
        : "+f"(c[0]),"+f"(c[1]),"+f"(c[2]),"+f"(c[3])
        : "r"(a[0]),"r"(a[1]),"r"(a[2]),"r"(a[3]),"r"(b0),"r"(b1));
}

// ---------------- stats zeroing (R11-identical) ----------------
__global__ void zero_stats_kernel() {
    int t = threadIdx.x;
    if (t < 5*128) { g_sum[t] = 0.f; g_sq[t] = 0.f; }
}

// ---------------- W fragment prep (R11-identical) ----------------
__device__ __forceinline__ uint32_t pack_bf2(float a, float b) {
    __nv_bfloat162 p; p.x = __float2bfloat16(a); p.y = __float2bfloat16(b);
    return *(uint32_t*)&p;
}
__device__ __forceinline__ void fill_wfrag(uint4* dst, const float* W, int N, int idx) {
    const int NT = N/8;
    int kt = idx/(NT*32); int rem = idx%(NT*32);
    int nt = rem/32;      int l  = rem%32;
    int grp = l>>2, tq = l&3;
    int col = nt*8 + grp;
    int k0 = kt*16 + 2*tq;
    float w00 = W[(k0  )*N+col], w01 = W[(k0+1)*N+col];
    float w10 = W[(k0+8)*N+col], w11 = W[(k0+9)*N+col];
    float h00 = __bfloat162float(__float2bfloat16(w00));
    float h01 = __bfloat162float(__float2bfloat16(w01));
    float h10 = __bfloat162float(__float2bfloat16(w10));
    float h11 = __bfloat162float(__float2bfloat16(w11));
    uint4 o;
    o.x = pack_bf2(w00, w01);
    o.y = pack_bf2(w10, w11);
    o.z = pack_bf2(w00-h00, w01-h01);
    o.w = pack_bf2(w10-h10, w11-h11);
    dst[idx] = o;
}
__global__ void prep_w_kernel(const float* __restrict__ W4, const float* __restrict__ W5) {
    int idx = blockIdx.x*256 + threadIdx.x;
    if (idx < 512)       fill_wfrag(g_W4f, W4, 64,  idx);
    else if (idx < 2560) fill_wfrag(g_W5f, W5, 128, idx-512);
}

// ---------------- build per-graph 8x8 aggregation matrix (R11-identical) ----------------
__global__ void __launch_bounds__(256) build_A_kernel(
    const int* __restrict__ ei, const float* __restrict__ ew, int E)
{
    __shared__ float          s_w[8][EPG];
    __shared__ unsigned char  s_s[8][EPG];
    __shared__ unsigned char  s_d[8][EPG];
    __shared__ float          s_dis[8][8];
    __shared__ float          s_A[8][64];

    const int warp = threadIdx.x >> 5, lane = threadIdx.x & 31;
    const int g = blockIdx.x * 8 + warp;
    const int* srcp = ei;
    const int* dstp = ei + E;
    const int ebase = g * EPG;
    const int nbase = g * NPG;

    for (int i = lane; i < EPG; i += 32) {
        s_s[warp][i] = (unsigned char)(srcp[ebase+i] - nbase);
        s_d[warp][i] = (unsigned char)(dstp[ebase+i] - nbase);
        s_w[warp][i] = ew[ebase+i];
    }
    __syncwarp();
    if (lane < 8) {
        float deg = 1.0f;
        for (int i = 0; i < EPG; i++)
            if (s_d[warp][i] == lane) deg += s_w[warp][i];
        s_dis[warp][lane] = rsqrtf(deg);
    }
    __syncwarp();
    if (lane < 8) {
        float dis = s_dis[warp][lane];
        s_A[warp][lane*8 + lane] = dis*dis;
    }
    for (int i = lane; i < EPG; i += 32) {
        int s = s_s[warp][i], d = s_d[warp][i];
        s_A[warp][d*8 + s] = s_dis[warp][s] * s_w[warp][i] * s_dis[warp][d];
    }
    __syncwarp();
    for (int i = lane; i < 64; i += 32) g_A[(size_t)g*64 + i] = s_A[warp][i];
}

// ---------------- fp32 layer kernel (R11-identical) ----------------
template<int D_IN, int D_IN_PAD, int D_OUT, int CH, int GPW, bool BN_IN,
         int IN_BUF, int OUT_BUF, int SIN, int SOUT>
__global__ void __launch_bounds__(256) layer_kernel(
    const float* __restrict__ xin_arg,
    const float* __restrict__ W, const float* __restrict__ bias,
    const float* __restrict__ in_g, const float* __restrict__ in_be)
{
    constexpr int GPB   = 8 * GPW;
    constexpr int NODES = GPB * NPG;
    constexpr int WSZ   = D_IN_PAD * D_OUT;
    constexpr int ZSZ   = NODES * D_IN_PAD;

    extern __shared__ float sm[];
    float* W_sh  = sm;
    float* z_sh  = W_sh + WSZ;
    float* A_sh  = z_sh + ZSZ;
    float* red   = A_sh + GPB*64;
    float* sc_sh = red + 2*D_OUT;
    float* sh_sh = sc_sh + D_IN;

    const float* xin = (IN_BUF > 0) ? buf_ptr<IN_BUF>() : xin_arg;
    float* yout = buf_ptr<OUT_BUF>();

    const int t = threadIdx.x;
    if (t < 2*D_OUT) red[t] = 0.f;
    if (BN_IN && t < D_IN) {
        const float inv_n = 1.0f / (float)NNODES;
        float m  = g_sum[SIN + t] * inv_n;
        float v  = g_sq [SIN + t] * inv_n - m*m;
        float sc = in_g[t] * rsqrtf(v + EPS_BN);
        sc_sh[t] = sc;
        sh_sh[t] = in_be[t] - m*sc;
    }
    for (int i = t; i < WSZ; i += 256) W_sh[i] = (i < D_IN*D_OUT) ? W[i] : 0.f;
    {
        const float* Ag = g_A + (size_t)blockIdx.x * (GPB*64);
        for (int i = t; i < GPB*64; i += 256) A_sh[i] = Ag[i];
    }
    __syncthreads();

    {
        const float* xb = xin + (size_t)blockIdx.x * NODES * D_IN;
        if (D_IN_PAD == D_IN && (D_IN % 4) == 0) {
            for (int i = t; i < NODES*D_IN/4; i += 256) {
                float4 v = reinterpret_cast<const float4*>(xb)[i];
                if (BN_IN) {
                    int c = (i*4) % D_IN;
                    v.x = lrelu(fmaf(sc_sh[c+0], v.x, sh_sh[c+0]));
                    v.y = lrelu(fmaf(sc_sh[c+1], v.y, sh_sh[c+1]));
                    v.z = lrelu(fmaf(sc_sh[c+2], v.z, sh_sh[c+2]));
                    v.w = lrelu(fmaf(sc_sh[c+3], v.w, sh_sh[c+3]));
                }
                reinterpret_cast<float4*>(z_sh)[i] = v;
            }
        } else {
            for (int i = t; i < ZSZ; i += 256) {
                int node = i / D_IN_PAD, c = i % D_IN_PAD;
                float v = 0.f;
                if (c < D_IN) {
                    v = xb[node*D_IN + c];
                    if (BN_IN) v = lrelu(fmaf(sc_sh[c], v, sh_sh[c]));
                }
                z_sh[i] = v;
            }
        }
    }
    __syncthreads();

    const int warp = t >> 5, lane = t & 31;
    int graph_l, c0;
    if constexpr (GPW == 2) { graph_l = warp*2 + (lane >> 4); c0 = (lane & 15) * CH; }
    else                    { graph_l = warp;                 c0 = lane * CH; }

    if (c0 < D_OUT) {
        float acc[NPG][CH];
        #pragma unroll
        for (int n = 0; n < NPG; n++)
            #pragma unroll
            for (int j = 0; j < CH; j++) acc[n][j] = 0.f;

        const float* zw = z_sh + graph_l * NPG * D_IN_PAD;
        #pragma unroll 4
        for (int k = 0; k < D_IN_PAD; k += 4) {
            float wv[4][CH];
            #pragma unroll
            for (int kk = 0; kk < 4; kk++) {
                const float* wr = W_sh + (k+kk)*D_OUT + c0;
                if constexpr (CH == 2) {
                    float2 w2 = *reinterpret_cast<const float2*>(wr);
                    wv[kk][0]=w2.x; wv[kk][1]=w2.y;
                } else {
                    wv[kk][0] = wr[0];
                }
            }
            #pragma unroll
            for (int n = 0; n < NPG; n++) {
                float4 z = *reinterpret_cast<const float4*>(zw + n*D_IN_PAD + k);
                #pragma unroll
                for (int j = 0; j < CH; j++)
                    acc[n][j] += z.x*wv[0][j] + z.y*wv[1][j] + z.z*wv[2][j] + z.w*wv[3][j];
            }
        }

        float bcol[CH], ssum[CH], ssq[CH];
        #pragma unroll
        for (int j = 0; j < CH; j++) { bcol[j] = bias[c0+j]; ssum[j]=0.f; ssq[j]=0.f; }

        const float* Aw = A_sh + graph_l*64;
        float* yb = yout + ((size_t)blockIdx.x*NODES + graph_l*NPG) * D_OUT + c0;
        #pragma unroll
        for (int n = 0; n < NPG; n++) {
            float y[CH];
            #pragma unroll
            for (int j = 0; j < CH; j++) y[j] = bcol[j];
            #pragma unroll
            for (int m = 0; m < NPG; m++) {
                float a = Aw[n*8 + m];
                #pragma unroll
                for (int j = 0; j < CH; j++) y[j] += a * acc[m][j];
            }
            #pragma unroll
            for (int j = 0; j < CH; j++) { ssum[j] += y[j]; ssq[j] += y[j]*y[j]; }
            float* yo = yb + n*D_OUT;
            if constexpr (CH == 2)
                *reinterpret_cast<float2*>(yo) = make_float2(y[0],y[1]);
            else
                yo[0] = y[0];
        }
        #pragma unroll
        for (int j = 0; j < CH; j++) {
            atomicAdd(&red[c0+j],        ssum[j]);
            atomicAdd(&red[D_OUT+c0+j],  ssq[j]);
        }
    }
    __syncthreads();
    if (t < D_OUT) {
        atomicAdd(&g_sum[SOUT + t], red[t]);
        atomicAdd(&g_sq [SOUT + t], red[D_OUT+t]);
    }
}

// ---------------- tensor-core layer (R11 + fp16 I/O change) ----------------
// IN_BUF: 3 = g_y3 (fp32), 4 = g_h4 (fp16). OUT_BUF: 4 = g_h4, 5 = g_h5.
template<int K, int N, int KP, int IN_BUF, int OUT_BUF, int SIN, int SOUT, int WSEL>
__global__ void __launch_bounds__(256) tc_layer_kernel(
    const float* __restrict__ bias,
    const float* __restrict__ in_g, const float* __restrict__ in_be)
{
    constexpr int ROWS = 128, GPB = 16;
    constexpr int KT = K/16, NT = N/8, ZP = ROWS + 1;

    extern __shared__ char smraw[];
    uint4* Wf      = (uint4*)smraw;
    float* z_t     = (float*)(Wf + KT*NT*32);
    float* A_sh    = z_t + K*ZP;
    float* bias_sh = A_sh + GPB*64;
    float* sc_sh   = bias_sh + N;
    float* sh_sh   = sc_sh + K;
    float* red     = sh_sh + K;
    float* redq    = red + N;
    __nv_bfloat16* vh = (__nv_bfloat16*)(redq + N);
    __nv_bfloat16* vl = vh + ROWS*KP;

    const int t = threadIdx.x;
    __half* yout = ((OUT_BUF == 4) ? g_h4 : g_h5) + (size_t)blockIdx.x * ROWS * N;

    for (int i = t; i < KT*NT*32; i += 256) Wf[i] = wf_ptr<WSEL>()[i];
    for (int i = t; i < GPB*64; i += 256) A_sh[i] = g_A[(size_t)blockIdx.x*GPB*64 + i];
    if (t < N) { bias_sh[t] = bias[t]; red[t] = 0.f; redq[t] = 0.f; }
    if (t < K) {
        const float inv_n = 1.0f / (float)NNODES;
        float m = g_sum[SIN + t] * inv_n;
        float v = g_sq [SIN + t] * inv_n - m*m;
        float s = in_g[t] * rsqrtf(v + EPS_BN);
        sc_sh[t] = s; sh_sh[t] = in_be[t] - m*s;
    }
    __syncthreads();

    // z = lrelu(bn(x)) transposed into z_t[k][row]
    if constexpr (IN_BUF == 3) {
        const float* xin = g_y3 + (size_t)blockIdx.x * ROWS * K;
        for (int i = t; i < ROWS*(K/4); i += 256) {
            int r = i / (K/4), k = (i % (K/4)) * 4;
            float4 v = *(const float4*)(xin + r*K + k);
            v.x = lrelu(fmaf(sc_sh[k+0], v.x, sh_sh[k+0]));
            v.y = lrelu(fmaf(sc_sh[k+1], v.y, sh_sh[k+1]));
            v.z = lrelu(fmaf(sc_sh[k+2], v.z, sh_sh[k+2]));
            v.w = lrelu(fmaf(sc_sh[k+3], v.w, sh_sh[k+3]));
            z_t[(k+0)*ZP + r] = v.x;
            z_t[(k+1)*ZP + r] = v.y;
            z_t[(k+2)*ZP + r] = v.z;
            z_t[(k+3)*ZP + r] = v.w;
        }
    } else {
        const __half* xin = g_h4 + (size_t)blockIdx.x * ROWS * K;
        for (int i = t; i < ROWS*(K/8); i += 256) {
            int r = i / (K/8), k = (i % (K/8)) * 8;
            uint4 raw = *(const uint4*)(xin + r*K + k);
            const __half2* hp = (const __half2*)&raw;
            #pragma unroll
            for (int j = 0; j < 4; j++) {
                float2 f = __half22float2(hp[j]);
                int kk = k + 2*j;
                z_t[(kk+0)*ZP + r] = lrelu(fmaf(sc_sh[kk+0], f.x, sh_sh[kk+0]));
                z_t[(kk+1)*ZP + r] = lrelu(fmaf(sc_sh[kk+1], f.y, sh_sh[kk+1]));
            }
        }
    }
    __syncthreads();

    // v = A @ z, split into bf16 hi/lo planes
    {
        int r = t & 127, h = t >> 7;
        int g = r >> 3, n = r & 7;
        float a[8];
        #pragma unroll
        for (int m = 0; m < 8; m++) a[m] = A_sh[g*64 + n*8 + m];
        const int k0 = h * (K/2);
        for (int k = k0; k < k0 + K/2; k += 2) {
            float v0 = 0.f, v1 = 0.f;
            #pragma unroll
            for (int m = 0; m < 8; m++) {
                float am = a[m];
                v0 = fmaf(am, z_t[(k  )*ZP + g*8 + m], v0);
                v1 = fmaf(am, z_t[(k+1)*ZP + g*8 + m], v1);
            }
            float h0 = __bfloat162float(__float2bfloat16(v0));
            float h1 = __bfloat162float(__float2bfloat16(v1));
            *(uint32_t*)(vh + r*KP + k) = pack_bf2(v0, v1);
            *(uint32_t*)(vl + r*KP + k) = pack_bf2(v0 - h0, v1 - h1);
        }
    }
    __syncthreads();

    // MMA: warp w -> rows [w*16, w*16+16)
    const int w = t >> 5, l = t & 31, grp = l >> 2, tq = l & 3;
    const int rowbase = w * 16;
    uint32_t ah[KT][4], al[KT][4];
    #pragma unroll
    for (int kt = 0; kt < KT; kt++) {
        int e0 = (rowbase + grp)*KP + kt*16 + 2*tq;
        int e1 = e0 + 8*KP;
        ah[kt][0] = *(const uint32_t*)(vh + e0);
        ah[kt][1] = *(const uint32_t*)(vh + e1);
        ah[kt][2] = *(const uint32_t*)(vh + e0 + 8);
        ah[kt][3] = *(const uint32_t*)(vh + e1 + 8);
        al[kt][0] = *(const uint32_t*)(vl + e0);
        al[kt][1] = *(const uint32_t*)(vl + e1);
        al[kt][2] = *(const uint32_t*)(vl + e0 + 8);
        al[kt][3] = *(const uint32_t*)(vl + e1 + 8);
    }
    #pragma unroll
    for (int nt = 0; nt < NT; nt++) {
        int c0 = nt*8 + 2*tq;
        float2 bb = *(const float2*)(bias_sh + c0);
        float c[4] = {bb.x, bb.y, bb.x, bb.y};
        #pragma unroll
        for (int kt = 0; kt < KT; kt++) {
            uint4 wfr = Wf[(kt*NT + nt)*32 + l];
            mma_bf16(c, ah[kt], wfr.x, wfr.y);
            mma_bf16(c, ah[kt], wfr.z, wfr.w);
            mma_bf16(c, al[kt], wfr.x, wfr.y);
        }
        __half* y0 = yout + (rowbase + grp)*N + c0;
        *(__half2*)y0         = __floats2half2_rn(c[0], c[1]);
        *(__half2*)(y0 + 8*N) = __floats2half2_rn(c[2], c[3]);
        float s0 = c[0]+c[2], s1 = c[1]+c[3];
        float q0 = c[0]*c[0]+c[2]*c[2], q1 = c[1]*c[1]+c[3]*c[3];
        #pragma unroll
        for (int m = 4; m < 32; m <<= 1) {
            s0 += __shfl_xor_sync(0xffffffffu, s0, m);
            s1 += __shfl_xor_sync(0xffffffffu, s1, m);
            q0 += __shfl_xor_sync(0xffffffffu, q0, m);
            q1 += __shfl_xor_sync(0xffffffffu, q1, m);
        }
        if (grp == 0) {
            atomicAdd(&red [c0],   s0); atomicAdd(&red [c0+1], s1);
            atomicAdd(&redq[c0],   q0); atomicAdd(&redq[c0+1], q1);
        }
    }
    __syncthreads();
    if (t < N) {
        atomicAdd(&g_sum[SOUT + t], red[t]);
        atomicAdd(&g_sq [SOUT + t], redq[t]);
    }
}

// ---------------- final: bn+lrelu on y5 (fp16), mean-pool, MLP ----------------
__global__ void __launch_bounds__(256) final_kernel(
    const float* __restrict__ g5, const float* __restrict__ be5,
    const float* __restrict__ fc1w, const float* __restrict__ fc1b,
    const float* __restrict__ fc2w, const float* __restrict__ fc2b,
    const float* __restrict__ ow,   const float* __restrict__ ob,
    float* __restrict__ out)
{
    __shared__ float sc[128], sh[128];
    __shared__ float w1s[128*30];
    __shared__ float b1s[30], w2s[30*20], b2s[20], w3s[20];
    __shared__ float P[8][128];
    __shared__ float Z1[8][30];

    const int t = threadIdx.x;
    if (t < 128) {
        const float inv_n = 1.0f / (float)NNODES;
        float m = g_sum[512 + t] * inv_n;
        float v = g_sq [512 + t] * inv_n - m*m;
        float s = g5[t] * rsqrtf(v + EPS_BN);
        sc[t] = s; sh[t] = be5[t] - m*s;
    }
    for (int i = t; i < 128*30; i += 256) w1s[i] = fc1w[i];
    if (t < 30) b1s[t] = fc1b[t];
    for (int i = t; i < 600; i += 256) w2s[i] = fc2w[i];
    if (t < 20) b2s[t] = fc2b[t];
    if (t < 20) w3s[t] = ow[t];
    __syncthreads();

    const int warp = t >> 5, lane = t & 31;
    const int g = blockIdx.x * 8 + warp;
    const int c0 = lane * 4;

    float p0=0.f, p1=0.f, p2=0.f, p3=0.f;
    const __half* yb = g_h5 + (size_t)g * NPG * 128 + c0;
    #pragma unroll
    for (int n = 0; n < NPG; n++) {
        uint2 raw = *(const uint2*)(yb + n*128);
        float2 f0 = __half22float2(*(const __half2*)&raw.x);
        float2 f1 = __half22float2(*(const __half2*)&raw.y);
        p0 += lrelu(fmaf(sc[c0+0], f0.x, sh[c0+0]));
        p1 += lrelu(fmaf(sc[c0+1], f0.y, sh[c0+1]));
        p2 += lrelu(fmaf(sc[c0+2], f1.x, sh[c0+2]));
        p3 += lrelu(fmaf(sc[c0+3], f1.y, sh[c0+3]));
    }
    const float inv8 = 1.0f / (float)NPG;
    P[warp][c0+0] = p0*inv8; P[warp][c0+1] = p1*inv8;
    P[warp][c0+2] = p2*inv8; P[warp][c0+3] = p3*inv8;
    __syncwarp();

    if (lane < 30) {
        float z1 = b1s[lane];
        #pragma unroll 8
        for (int k = 0; k < 128; k++) z1 += P[warp][k] * w1s[k*30 + lane];
        Z1[warp][lane] = lrelu(z1);
    }
    __syncwarp();

    float z2 = 0.f;
    if (lane < 20) {
        float a = b2s[lane];
        #pragma unroll
        for (int k = 0; k < 30; k++) a += Z1[warp][k] * w2s[k*20 + lane];
        z2 = lrelu(a) * w3s[lane];
    }
    #pragma unroll
    for (int off = 16; off > 0; off >>= 1)
        z2 += __shfl_down_sync(0xffffffffu, z2, off);
    if (lane == 0) out[g] = z2 + ob[0];
}

// ---------------- launch (R11-identical) ----------------
static constexpr int smem_small(int din, int dinp, int dout, int gpb) {
    return (dinp*dout + gpb*8*dinp + gpb*64 + 2*dout + 2*din) * 4;
}
static constexpr int smem_tc(int K, int N, int KP) {
    return (K/16)*(N/8)*32*16
         + K*(128+1)*4
         + 16*64*4
         + (N + 2*K + 2*N)*4
         + 2*128*KP*2;
}

extern "C" void kernel_launch(void* const* d_in, const int* in_sizes, int n_in,
                              void* d_out, int out_size)
{
    const float* x   = (const float*)d_in[0];
    const int*   ei  = (const int*)  d_in[1];
    const float* ea  = (const float*)d_in[2];
    const float* w1  = (const float*)d_in[4],  *b1  = (const float*)d_in[5];
    const float* ga1 = (const float*)d_in[6],  *be1 = (const float*)d_in[7];
    const float* w2  = (const float*)d_in[8],  *b2  = (const float*)d_in[9];
    const float* ga2 = (const float*)d_in[10], *be2 = (const float*)d_in[11];
    const float* w3  = (const float*)d_in[12], *b3  = (const float*)d_in[13];
    const float* ga3 = (const float*)d_in[14], *be3 = (const float*)d_in[15];
    const float* w4  = (const float*)d_in[16], *b4  = (const float*)d_in[17];
    const float* ga4 = (const float*)d_in[18], *be4 = (const float*)d_in[19];
    const float* w5  = (const float*)d_in[20], *b5  = (const float*)d_in[21];
    const float* ga5 = (const float*)d_in[22], *be5 = (const float*)d_in[23];
    const float* fc1w = (const float*)d_in[24], *fc1b = (const float*)d_in[25];
    const float* fc2w = (const float*)d_in[26], *fc2b = (const float*)d_in[27];
    const float* ow   = (const float*)d_in[28], *ob   = (const float*)d_in[29];
    float* out = (float*)d_out;

    const int E = in_sizes[1] / 2;

    cudaFuncSetAttribute(tc_layer_kernel<32, 64,40,3,4,256,384,4>,
                         cudaFuncAttributeMaxDynamicSharedMemorySize, smem_tc(32,64,40));
    cudaFuncSetAttribute(tc_layer_kernel<64,128,72,4,5,384,512,5>,
                         cudaFuncAttributeMaxDynamicSharedMemorySize, smem_tc(64,128,72));

    zero_stats_kernel<<<1, 640>>>();
    build_A_kernel<<<NGR/8, 256>>>(ei, ea, E);
    prep_w_kernel<<<10, 256>>>(w4, w5);

    layer_kernel< 6,  8, 16, 1, 2, false, 0, 1,   0,   0>
        <<<NGR/16, 256, smem_small(6,8,16,16)>>>(x, w1, b1, nullptr, nullptr);
    layer_kernel<16, 16, 16, 1, 2, true,  1, 2,   0, 128>
        <<<NGR/16, 256, smem_small(16,16,16,16)>>>(nullptr, w2, b2, ga1, be1);
    layer_kernel<16, 16, 32, 1, 1, true,  2, 3, 128, 256>
        <<<NGR/8, 256, smem_small(16,16,32,8)>>>(nullptr, w3, b3, ga2, be2);

    tc_layer_kernel<32, 64, 40, 3, 4, 256, 384, 4>
        <<<NNODES/128, 256, smem_tc(32,64,40)>>>(b4, ga3, be3);
    tc_layer_kernel<64,128, 72, 4, 5, 384, 512, 5>
        <<<NNODES/128, 256, smem_tc(64,128,72)>>>(b5, ga4, be4);

    final_kernel<<<NGR/8, 256>>>(ga5, be5, fc1w, fc1b, fc2w, fc2b, ow, ob, out);
}

// round 17
// speedup vs baseline: 1.1187x; 1.0330x over previous
#include <cuda_runtime.h>
#include <cuda_bf16.h>
#include <cuda_fp16.h>
#include <cstdint>

#define NGR 16384
#define NPG 8
#define NNODES (NGR*NPG)
#define EPG 56
#define EPS_BN 1e-5f
#define SLOPE 0.01f

// ---------------- device scratch ----------------
__device__ float  g_A[NGR*64];
__device__ float  g_y1[NNODES*16];
__device__ float  g_y2[NNODES*16];
__device__ float  g_y3[NNODES*32];
__device__ __half g_h4[NNODES*64];
__device__ __half g_h5[NNODES*128];
__device__ float  g_sum[5*128];
__device__ float  g_sq [5*128];
__device__ uint4  g_W4f[2*8*32];
__device__ uint4  g_W5f[4*16*32];

__device__ __forceinline__ float lrelu(float x) { return x >= 0.f ? x : SLOPE*x; }

template<int IDX> __device__ __forceinline__ float* buf_ptr() {
    if constexpr (IDX == 1) return g_y1;
    else if constexpr (IDX == 2) return g_y2;
    else return g_y3;
}
template<int SEL> __device__ __forceinline__ const uint4* wf_ptr() {
    if constexpr (SEL == 4) return g_W4f; else return g_W5f;
}

__device__ __forceinline__ void mma_bf16(float* c, const uint32_t* a, uint32_t b0, uint32_t b1) {
    asm volatile("mma.sync.aligned.m16n8k16.row.col.f32.bf16.bf16.f32 "
        "{%0,%1,%2,%3},{%4,%5,%6,%7},{%8,%9},{%0,%1,%2,%3};"
        : "+f"(c[0]),"+f"(c[1]),"+f"(c[2]),"+f"(c[3])
        : "r"(a[0]),"r"(a[1]),"r"(a[2]),"r"(a[3]),"r"(b0),"r"(b1));
}

__device__ __forceinline__ uint32_t pack_bf2(float a, float b) {
    __nv_bfloat162 p; p.x = __float2bfloat16(a); p.y = __float2bfloat16(b);
    return *(uint32_t*)&p;
}

// ---------------- setup: W fragments + stats zero (merged) ----------------
__device__ __forceinline__ void fill_wfrag(uint4* dst, const float* W, int N, int idx) {
    const int NT = N/8;
    int kt = idx/(NT*32); int rem = idx%(NT*32);
    int nt = rem/32;      int l  = rem%32;
    int grp = l>>2, tq = l&3;
    int col = nt*8 + grp;
    int k0 = kt*16 + 2*tq;
    float w00 = W[(k0  )*N+col], w01 = W[(k0+1)*N+col];
    float w10 = W[(k0+8)*N+col], w11 = W[(k0+9)*N+col];
    float h00 = __bfloat162float(__float2bfloat16(w00));
    float h01 = __bfloat162float(__float2bfloat16(w01));
    float h10 = __bfloat162float(__float2bfloat16(w10));
    float h11 = __bfloat162float(__float2bfloat16(w11));
    uint4 o;
    o.x = pack_bf2(w00, w01);
    o.y = pack_bf2(w10, w11);
    o.z = pack_bf2(w00-h00, w01-h01);
    o.w = pack_bf2(w10-h10, w11-h11);
    dst[idx] = o;
}
__global__ void setup_kernel(const float* __restrict__ W4, const float* __restrict__ W5) {
    int b = blockIdx.x, t = threadIdx.x;
    if (b < 10) {
        int idx = b*256 + t;
        if (idx < 512) fill_wfrag(g_W4f, W4, 64, idx);
        else           fill_wfrag(g_W5f, W5, 128, idx-512);
    } else {
        for (int i = t; i < 5*128; i += 256) { g_sum[i] = 0.f; g_sq[i] = 0.f; }
    }
}

// ---------------- small fp32 layer: GPB = 8*GPW graphs/block, optional A build ----------------
template<int D_IN, int D_IN_PAD, int D_OUT, int GPW, bool BUILD, bool BN_IN,
         int IN_BUF, int OUT_BUF, int SIN, int SOUT>
__global__ void __launch_bounds__(256) small_layer_kernel(
    const float* __restrict__ xin_arg,
    const int* __restrict__ ei, const float* __restrict__ ew, int E,
    const float* __restrict__ W, const float* __restrict__ bias,
    const float* __restrict__ in_g, const float* __restrict__ in_be)
{
    constexpr int GPB   = 8 * GPW;         // graphs per block (FULL coverage: 8 warps * GPW)
    constexpr int NODES = GPB * NPG;
    constexpr int WSZ   = D_IN_PAD * D_OUT;
    constexpr int ZSZ   = NODES * D_IN_PAD;
    constexpr int CH    = D_OUT*GPW/32;    // 2 in all instantiations
    constexpr int LPG   = 32/GPW;

    extern __shared__ float sm[];
    float* W_sh  = sm;                     // WSZ
    float* A_sh  = W_sh + WSZ;             // GPB*64
    float* red   = A_sh + GPB*64;          // 2*D_OUT
    float* sc_sh = red + 2*D_OUT;          // D_IN
    float* sh_sh = sc_sh + D_IN;           // D_IN
    float* z_sh  = sh_sh + D_IN;           // union: z (ZSZ) / edge staging

    const float* xin = (IN_BUF > 0) ? buf_ptr<IN_BUF>() : xin_arg;
    float* yout = buf_ptr<OUT_BUF>();

    const int t = threadIdx.x;
    if (t < 2*D_OUT) red[t] = 0.f;
    if (BN_IN && t < D_IN) {
        const float inv_n = 1.0f / (float)NNODES;
        float m  = g_sum[SIN + t] * inv_n;
        float v  = g_sq [SIN + t] * inv_n - m*m;
        float sc = in_g[t] * rsqrtf(v + EPS_BN);
        sc_sh[t] = sc;
        sh_sh[t] = in_be[t] - m*sc;
    }
    for (int i = t; i < WSZ; i += 256) W_sh[i] = (i < D_IN*D_OUT) ? W[i] : 0.f;

    if constexpr (BUILD) {
        float* e_w   = z_sh;                                  // GPB*EPG floats
        float* e_dis = z_sh + GPB*EPG;                        // GPB*8 floats
        unsigned char* e_s = (unsigned char*)(e_dis + GPB*8);
        unsigned char* e_d = e_s + GPB*EPG;
        const int ebase = blockIdx.x * GPB * EPG;
        for (int i = t; i < GPB*EPG; i += 256) {
            int gl = i / EPG;
            int nb = (blockIdx.x*GPB + gl) * NPG;
            e_s[i] = (unsigned char)(ei[ebase+i] - nb);
            e_d[i] = (unsigned char)(ei[E + ebase+i] - nb);
            e_w[i] = ew[ebase+i];
        }
        __syncthreads();
        if (t < GPB*8) {
            int gl = t >> 3, n = t & 7;
            float deg = 1.f;
            const int eb = gl*EPG;
            #pragma unroll 8
            for (int e = 0; e < EPG; e++)
                deg += (e_d[eb+e] == n) ? e_w[eb+e] : 0.f;
            float dis = rsqrtf(deg);
            e_dis[t] = dis;
            A_sh[gl*64 + n*8 + n] = dis*dis;
        }
        __syncthreads();
        for (int i = t; i < GPB*EPG; i += 256) {
            int gl = i/EPG; int s = e_s[i], d = e_d[i];
            A_sh[gl*64 + d*8 + s] = e_dis[gl*8+s]*e_w[i]*e_dis[gl*8+d];
        }
        __syncthreads();
        for (int i = t; i < GPB*64; i += 256)
            g_A[(size_t)blockIdx.x*GPB*64 + i] = A_sh[i];
        __syncthreads();   // staging area about to be overwritten by z
    } else {
        const float* Ag = g_A + (size_t)blockIdx.x * GPB * 64;
        for (int i = t; i < GPB*64; i += 256) A_sh[i] = Ag[i];
        __syncthreads();
    }

    // z = lrelu(bn(x)) (or raw x for layer 1)
    {
        const float* xb = xin + (size_t)blockIdx.x * NODES * D_IN;
        if (D_IN_PAD == D_IN && (D_IN % 4) == 0) {
            for (int i = t; i < NODES*D_IN/4; i += 256) {
                float4 v = reinterpret_cast<const float4*>(xb)[i];
                if (BN_IN) {
                    int c = (i*4) % D_IN;
                    v.x = lrelu(fmaf(sc_sh[c+0], v.x, sh_sh[c+0]));
                    v.y = lrelu(fmaf(sc_sh[c+1], v.y, sh_sh[c+1]));
                    v.z = lrelu(fmaf(sc_sh[c+2], v.z, sh_sh[c+2]));
                    v.w = lrelu(fmaf(sc_sh[c+3], v.w, sh_sh[c+3]));
                }
                reinterpret_cast<float4*>(z_sh)[i] = v;
            }
        } else {
            for (int i = t; i < ZSZ; i += 256) {
                int node = i / D_IN_PAD, c = i % D_IN_PAD;
                float v = 0.f;
                if (c < D_IN) {
                    v = xb[node*D_IN + c];
                    if (BN_IN) v = lrelu(fmaf(sc_sh[c], v, sh_sh[c]));
                }
                z_sh[i] = v;
            }
        }
    }
    __syncthreads();

    // compute: warp handles GPW graphs, LPG lanes per graph, CH=2 cols per lane
    {
        const int w = t >> 5, l = t & 31;
        const int gl = w*GPW + l/LPG;       // covers 0..GPB-1 exactly
        const int c0 = (l % LPG) * CH;

        float acc[NPG][CH];
        #pragma unroll
        for (int n = 0; n < NPG; n++)
            #pragma unroll
            for (int j = 0; j < CH; j++) acc[n][j] = 0.f;

        const float* zw = z_sh + gl * NPG * D_IN_PAD;
        #pragma unroll
        for (int k = 0; k < D_IN_PAD; k += 4) {
            float2 wv[4];
            #pragma unroll
            for (int kk = 0; kk < 4; kk++)
                wv[kk] = *reinterpret_cast<const float2*>(W_sh + (k+kk)*D_OUT + c0);
            #pragma unroll
            for (int n = 0; n < NPG; n++) {
                float4 z = *reinterpret_cast<const float4*>(zw + n*D_IN_PAD + k);
                acc[n][0] += z.x*wv[0].x + z.y*wv[1].x + z.z*wv[2].x + z.w*wv[3].x;
                acc[n][1] += z.x*wv[0].y + z.y*wv[1].y + z.z*wv[2].y + z.w*wv[3].y;
            }
        }

        float b0 = bias[c0], b1 = bias[c0+1];
        float ssum0=0.f, ssum1=0.f, ssq0=0.f, ssq1=0.f;
        const float* Aw = A_sh + gl*64;
        float* yb = yout + ((size_t)(blockIdx.x*GPB + gl)*NPG) * D_OUT + c0;
        #pragma unroll
        for (int n = 0; n < NPG; n++) {
            float y0 = b0, y1 = b1;
            #pragma unroll
            for (int m = 0; m < NPG; m++) {
                float a = Aw[n*8 + m];
                y0 = fmaf(a, acc[m][0], y0);
                y1 = fmaf(a, acc[m][1], y1);
            }
            ssum0 += y0; ssum1 += y1;
            ssq0 = fmaf(y0,y0,ssq0); ssq1 = fmaf(y1,y1,ssq1);
            *reinterpret_cast<float2*>(yb + n*D_OUT) = make_float2(y0, y1);
        }
        atomicAdd(&red[c0],          ssum0);
        atomicAdd(&red[c0+1],        ssum1);
        atomicAdd(&red[D_OUT+c0],    ssq0);
        atomicAdd(&red[D_OUT+c0+1],  ssq1);
    }
    __syncthreads();
    if (t < D_OUT) {
        atomicAdd(&g_sum[SOUT + t], red[t]);
        atomicAdd(&g_sq [SOUT + t], red[D_OUT+t]);
    }
}

// ---------------- tensor-core layer (R16-identical) ----------------
template<int K, int N, int KP, int IN_BUF, int OUT_BUF, int SIN, int SOUT, int WSEL>
__global__ void __launch_bounds__(256) tc_layer_kernel(
    const float* __restrict__ bias,
    const float* __restrict__ in_g, const float* __restrict__ in_be)
{
    constexpr int ROWS = 128, GPB = 16;
    constexpr int KT = K/16, NT = N/8, ZP = ROWS + 1;

    extern __shared__ char smraw[];
    uint4* Wf      = (uint4*)smraw;
    float* z_t     = (float*)(Wf + KT*NT*32);
    float* A_sh    = z_t + K*ZP;
    float* bias_sh = A_sh + GPB*64;
    float* sc_sh   = bias_sh + N;
    float* sh_sh   = sc_sh + K;
    float* red     = sh_sh + K;
    float* redq    = red + N;
    __nv_bfloat16* vh = (__nv_bfloat16*)(redq + N);
    __nv_bfloat16* vl = vh + ROWS*KP;

    const int t = threadIdx.x;
    __half* yout = ((OUT_BUF == 4) ? g_h4 : g_h5) + (size_t)blockIdx.x * ROWS * N;

    for (int i = t; i < KT*NT*32; i += 256) Wf[i] = wf_ptr<WSEL>()[i];
    for (int i = t; i < GPB*64; i += 256) A_sh[i] = g_A[(size_t)blockIdx.x*GPB*64 + i];
    if (t < N) { bias_sh[t] = bias[t]; red[t] = 0.f; redq[t] = 0.f; }
    if (t < K) {
        const float inv_n = 1.0f / (float)NNODES;
        float m = g_sum[SIN + t] * inv_n;
        float v = g_sq [SIN + t] * inv_n - m*m;
        float s = in_g[t] * rsqrtf(v + EPS_BN);
        sc_sh[t] = s; sh_sh[t] = in_be[t] - m*s;
    }
    __syncthreads();

    if constexpr (IN_BUF == 3) {
        const float* xin = g_y3 + (size_t)blockIdx.x * ROWS * K;
        for (int i = t; i < ROWS*(K/4); i += 256) {
            int r = i / (K/4), k = (i % (K/4)) * 4;
            float4 v = *(const float4*)(xin + r*K + k);
            v.x = lrelu(fmaf(sc_sh[k+0], v.x, sh_sh[k+0]));
            v.y = lrelu(fmaf(sc_sh[k+1], v.y, sh_sh[k+1]));
            v.z = lrelu(fmaf(sc_sh[k+2], v.z, sh_sh[k+2]));
            v.w = lrelu(fmaf(sc_sh[k+3], v.w, sh_sh[k+3]));
            z_t[(k+0)*ZP + r] = v.x;
            z_t[(k+1)*ZP + r] = v.y;
            z_t[(k+2)*ZP + r] = v.z;
            z_t[(k+3)*ZP + r] = v.w;
        }
    } else {
        const __half* xin = g_h4 + (size_t)blockIdx.x * ROWS * K;
        for (int i = t; i < ROWS*(K/8); i += 256) {
            int r = i / (K/8), k = (i % (K/8)) * 8;
            uint4 raw = *(const uint4*)(xin + r*K + k);
            const __half2* hp = (const __half2*)&raw;
            #pragma unroll
            for (int j = 0; j < 4; j++) {
                float2 f = __half22float2(hp[j]);
                int kk = k + 2*j;
                z_t[(kk+0)*ZP + r] = lrelu(fmaf(sc_sh[kk+0], f.x, sh_sh[kk+0]));
                z_t[(kk+1)*ZP + r] = lrelu(fmaf(sc_sh[kk+1], f.y, sh_sh[kk+1]));
            }
        }
    }
    __syncthreads();

    {
        int r = t & 127, h = t >> 7;
        int g = r >> 3, n = r & 7;
        float a[8];
        #pragma unroll
        for (int m = 0; m < 8; m++) a[m] = A_sh[g*64 + n*8 + m];
        const int k0 = h * (K/2);
        for (int k = k0; k < k0 + K/2; k += 2) {
            float v0 = 0.f, v1 = 0.f;
            #pragma unroll
            for (int m = 0; m < 8; m++) {
                float am = a[m];
                v0 = fmaf(am, z_t[(k  )*ZP + g*8 + m], v0);
                v1 = fmaf(am, z_t[(k+1)*ZP + g*8 + m], v1);
            }
            float h0 = __bfloat162float(__float2bfloat16(v0));
            float h1 = __bfloat162float(__float2bfloat16(v1));
            *(uint32_t*)(vh + r*KP + k) = pack_bf2(v0, v1);
            *(uint32_t*)(vl + r*KP + k) = pack_bf2(v0 - h0, v1 - h1);
        }
    }
    __syncthreads();

    const int w = t >> 5, l = t & 31, grp = l >> 2, tq = l & 3;
    const int rowbase = w * 16;
    uint32_t ah[KT][4], al[KT][4];
    #pragma unroll
    for (int kt = 0; kt < KT; kt++) {
        int e0 = (rowbase + grp)*KP + kt*16 + 2*tq;
        int e1 = e0 + 8*KP;
        ah[kt][0] = *(const uint32_t*)(vh + e0);
        ah[kt][1] = *(const uint32_t*)(vh + e1);
        ah[kt][2] = *(const uint32_t*)(vh + e0 + 8);
        ah[kt][3] = *(const uint32_t*)(vh + e1 + 8);
        al[kt][0] = *(const uint32_t*)(vl + e0);
        al[kt][1] = *(const uint32_t*)(vl + e1);
        al[kt][2] = *(const uint32_t*)(vl + e0 + 8);
        al[kt][3] = *(const uint32_t*)(vl + e1 + 8);
    }
    #pragma unroll
    for (int nt = 0; nt < NT; nt++) {
        int c0 = nt*8 + 2*tq;
        float2 bb = *(const float2*)(bias_sh + c0);
        float c[4] = {bb.x, bb.y, bb.x, bb.y};
        #pragma unroll
        for (int kt = 0; kt < KT; kt++) {
            uint4 wfr = Wf[(kt*NT + nt)*32 + l];
            mma_bf16(c, ah[kt], wfr.x, wfr.y);
            mma_bf16(c, ah[kt], wfr.z, wfr.w);
            mma_bf16(c, al[kt], wfr.x, wfr.y);
        }
        __half* y0 = yout + (rowbase + grp)*N + c0;
        *(__half2*)y0         = __floats2half2_rn(c[0], c[1]);
        *(__half2*)(y0 + 8*N) = __floats2half2_rn(c[2], c[3]);
        float s0 = c[0]+c[2], s1 = c[1]+c[3];
        float q0 = c[0]*c[0]+c[2]*c[2], q1 = c[1]*c[1]+c[3]*c[3];
        #pragma unroll
        for (int m = 4; m < 32; m <<= 1) {
            s0 += __shfl_xor_sync(0xffffffffu, s0, m);
            s1 += __shfl_xor_sync(0xffffffffu, s1, m);
            q0 += __shfl_xor_sync(0xffffffffu, q0, m);
            q1 += __shfl_xor_sync(0xffffffffu, q1, m);
        }
        if (grp == 0) {
            atomicAdd(&red [c0],   s0); atomicAdd(&red [c0+1], s1);
            atomicAdd(&redq[c0],   q0); atomicAdd(&redq[c0+1], q1);
        }
    }
    __syncthreads();
    if (t < N) {
        atomicAdd(&g_sum[SOUT + t], red[t]);
        atomicAdd(&g_sq [SOUT + t], redq[t]);
    }
}

// ---------------- final (R16-identical) ----------------
__global__ void __launch_bounds__(256) final_kernel(
    const float* __restrict__ g5, const float* __restrict__ be5,
    const float* __restrict__ fc1w, const float* __restrict__ fc1b,
    const float* __restrict__ fc2w, const float* __restrict__ fc2b,
    const float* __restrict__ ow,   const float* __restrict__ ob,
    float* __restrict__ out)
{
    __shared__ float sc[128], sh[128];
    __shared__ float w1s[128*30];
    __shared__ float b1s[30], w2s[30*20], b2s[20], w3s[20];
    __shared__ float P[8][128];
    __shared__ float Z1[8][30];

    const int t = threadIdx.x;
    if (t < 128) {
        const float inv_n = 1.0f / (float)NNODES;
        float m = g_sum[512 + t] * inv_n;
        float v = g_sq [512 + t] * inv_n - m*m;
        float s = g5[t] * rsqrtf(v + EPS_BN);
        sc[t] = s; sh[t] = be5[t] - m*s;
    }
    for (int i = t; i < 128*30; i += 256) w1s[i] = fc1w[i];
    if (t < 30) b1s[t] = fc1b[t];
    for (int i = t; i < 600; i += 256) w2s[i] = fc2w[i];
    if (t < 20) b2s[t] = fc2b[t];
    if (t < 20) w3s[t] = ow[t];
    __syncthreads();

    const int warp = t >> 5, lane = t & 31;
    const int g = blockIdx.x * 8 + warp;
    const int c0 = lane * 4;

    float p0=0.f, p1=0.f, p2=0.f, p3=0.f;
    const __half* yb = g_h5 + (size_t)g * NPG * 128 + c0;
    #pragma unroll
    for (int n = 0; n < NPG; n++) {
        uint2 raw = *(const uint2*)(yb + n*128);
        float2 f0 = __half22float2(*(const __half2*)&raw.x);
        float2 f1 = __half22float2(*(const __half2*)&raw.y);
        p0 += lrelu(fmaf(sc[c0+0], f0.x, sh[c0+0]));
        p1 += lrelu(fmaf(sc[c0+1], f0.y, sh[c0+1]));
        p2 += lrelu(fmaf(sc[c0+2], f1.x, sh[c0+2]));
        p3 += lrelu(fmaf(sc[c0+3], f1.y, sh[c0+3]));
    }
    const float inv8 = 1.0f / (float)NPG;
    P[warp][c0+0] = p0*inv8; P[warp][c0+1] = p1*inv8;
    P[warp][c0+2] = p2*inv8; P[warp][c0+3] = p3*inv8;
    __syncwarp();

    if (lane < 30) {
        float z1 = b1s[lane];
        #pragma unroll 8
        for (int k = 0; k < 128; k++) z1 += P[warp][k] * w1s[k*30 + lane];
        Z1[warp][lane] = lrelu(z1);
    }
    __syncwarp();

    float z2 = 0.f;
    if (lane < 20) {
        float a = b2s[lane];
        #pragma unroll
        for (int k = 0; k < 30; k++) a += Z1[warp][k] * w2s[k*20 + lane];
        z2 = lrelu(a) * w3s[lane];
    }
    #pragma unroll
    for (int off = 16; off > 0; off >>= 1)
        z2 += __shfl_down_sync(0xffffffffu, z2, off);
    if (lane == 0) out[g] = z2 + ob[0];
}

// ---------------- launch ----------------
static constexpr int smem_small(int din, int dinp, int dout, int gpw, bool build) {
    int gpb  = 8*gpw;
    int base = (dinp*dout + gpb*64 + 2*dout + 2*din) * 4;
    int zby  = gpb*8*dinp*4;
    int eby  = (gpb*EPG + gpb*8)*4 + 2*gpb*EPG;
    int un   = (build && eby > zby) ? eby : zby;
    return base + un;
}
static constexpr int smem_tc(int K, int N, int KP) {
    return (K/16)*(N/8)*32*16
         + K*(128+1)*4
         + 16*64*4
         + (N + 2*K + 2*N)*4
         + 2*128*KP*2;
}

extern "C" void kernel_launch(void* const* d_in, const int* in_sizes, int n_in,
                              void* d_out, int out_size)
{
    const float* x   = (const float*)d_in[0];
    const int*   ei  = (const int*)  d_in[1];
    const float* ea  = (const float*)d_in[2];
    const float* w1  = (const float*)d_in[4],  *b1  = (const float*)d_in[5];
    const float* ga1 = (const float*)d_in[6],  *be1 = (const float*)d_in[7];
    const float* w2  = (const float*)d_in[8],  *b2  = (const float*)d_in[9];
    const float* ga2 = (const float*)d_in[10], *be2 = (const float*)d_in[11];
    const float* w3  = (const float*)d_in[12], *b3  = (const float*)d_in[13];
    const float* ga3 = (const float*)d_in[14], *be3 = (const float*)d_in[15];
    const float* w4  = (const float*)d_in[16], *b4  = (const float*)d_in[17];
    const float* ga4 = (const float*)d_in[18], *be4 = (const float*)d_in[19];
    const float* w5  = (const float*)d_in[20], *b5  = (const float*)d_in[21];
    const float* ga5 = (const float*)d_in[22], *be5 = (const float*)d_in[23];
    const float* fc1w = (const float*)d_in[24], *fc1b = (const float*)d_in[25];
    const float* fc2w = (const float*)d_in[26], *fc2b = (const float*)d_in[27];
    const float* ow   = (const float*)d_in[28], *ob   = (const float*)d_in[29];
    float* out = (float*)d_out;

    const int E = in_sizes[1] / 2;

    cudaFuncSetAttribute(tc_layer_kernel<32, 64,40,3,4,256,384,4>,
                         cudaFuncAttributeMaxDynamicSharedMemorySize, smem_tc(32,64,40));
    cudaFuncSetAttribute(tc_layer_kernel<64,128,72,4,5,384,512,5>,
                         cudaFuncAttributeMaxDynamicSharedMemorySize, smem_tc(64,128,72));

    setup_kernel<<<11, 256>>>(w4, w5);

    // L1: GPW=4 -> GPB=32, fused A build
    small_layer_kernel< 6,  8, 16, 4, true,  false, 0, 1,   0,   0>
        <<<NGR/32, 256, smem_small(6,8,16,4,true)>>>(x, ei, ea, E, w1, b1, nullptr, nullptr);
    // L2: GPW=4 -> GPB=32
    small_layer_kernel<16, 16, 16, 4, false, true,  1, 2,   0, 128>
        <<<NGR/32, 256, smem_small(16,16,16,4,false)>>>(nullptr, ei, ea, E, w2, b2, ga1, be1);
    // L3: GPW=2 -> GPB=16 (R12 bug was GPB=32 here: half the graphs uncomputed)
    small_layer_kernel<16, 16, 32, 2, false, true,  2, 3, 128, 256>
        <<<NGR/16, 256, smem_small(16,16,32,2,false)>>>(nullptr, ei, ea, E, w3, b3, ga2, be2);

    tc_layer_kernel<32, 64, 40, 3, 4, 256, 384, 4>
        <<<NNODES/128, 256, smem_tc(32,64,40)>>>(b4, ga3, be3);
    tc_layer_kernel<64,128, 72, 4, 5, 384, 512, 5>
        <<<NNODES/128, 256, smem_tc(64,128,72)>>>(b5, ga4, be4);

    final_kernel<<<NGR/8, 256>>>(ga5, be5, fc1w, fc1b, fc2w, fc2b, ow, ob, out);
}